// round 14
// baseline (speedup 1.0000x reference)
#include <cuda_runtime.h>
#include <cuda_fp16.h>
#include <cstdint>
#include <math.h>

// POLY2: out_b = sigmoid( sum_{i<j} w_ij * x_bi * x_bj )
// fp16 mma m16n8k16 accumulating DIRECTLY into running fp16 accH (C-operand),
// ldmatrix.x4, 2-stage cp.async, 3 CTAs/SM (24 warps - latency-bound relief),
// triangular K-skip + diagonal sub-block skip, heavy-tile-first.

#define F        1024
#define BATCHN   16384
#define M_TILE   128
#define N_TILE   128
#define K_CHUNK  64
#define NTHREADS 256
#define NBLK     8

#define ROW_B       144
#define TILE_BYTES  (128 * ROW_B)            // 18432
#define STAGE_BYTES (2 * TILE_BYTES)         // 36864
#define PART_OFF    (2 * STAGE_BYTES)        // 73728
#define SMEM_TOTAL  (PART_OFF + 128 * 4)     // 74240  (x3 CTAs = 222.7KB/SM)

__device__ __half d_Xh[BATCHN * F];
__device__ __half d_Wth[F * F];           // Wt[n][k] = w_{k,n} (k<n else 0)
__device__ float  d_part[NBLK * BATCHN];

// ---------------- helpers ----------------
__device__ __forceinline__ uint32_t smem_u32(const void* p) {
    uint32_t a;
    asm("{ .reg .u64 t; cvta.to.shared.u64 t, %1; cvt.u32.u64 %0, t; }" : "=r"(a) : "l"(p));
    return a;
}
__device__ __forceinline__ void cp16(uint32_t dst, const void* src) {
    asm volatile("cp.async.cg.shared.global [%0], [%1], 16;" :: "r"(dst), "l"(src) : "memory");
}
__device__ __forceinline__ void cp_commit() { asm volatile("cp.async.commit_group;" ::: "memory"); }
__device__ __forceinline__ void cp_wait1()  { asm volatile("cp.async.wait_group 1;"  ::: "memory"); }

__device__ __forceinline__ void ldsm4(uint32_t* r, uint32_t addr) {
    asm volatile("ldmatrix.sync.aligned.m8n8.x4.shared.b16 {%0,%1,%2,%3}, [%4];"
        : "=r"(r[0]), "=r"(r[1]), "=r"(r[2]), "=r"(r[3]) : "r"(addr));
}
// fp16 mma accumulating in-place into running accumulator (C = D = acc)
__device__ __forceinline__ void mma_h(uint32_t* c, const uint32_t* a, uint32_t b0, uint32_t b1) {
    asm volatile(
        "mma.sync.aligned.m16n8k16.row.col.f16.f16.f16.f16 "
        "{%0,%1}, {%2,%3,%4,%5}, {%6,%7}, {%0,%1};"
        : "+r"(c[0]), "+r"(c[1])
        : "r"(a[0]), "r"(a[1]), "r"(a[2]), "r"(a[3]), "r"(b0), "r"(b1));
}

// ---------------- merged prep ----------------
__device__ __forceinline__ float w_at(const float* __restrict__ w, int k, int n) {
    if (k >= n) return 0.0f;
    int pi = k * (F - 1) - (k * (k - 1)) / 2 + (n - k - 1);
    return w[pi];
}
#define CONV_BLOCKS (BATCHN * F / (256 * 16))         // 4096
#define WT_BLOCKS   (F * F / 2 / 256)                 // 2048

__global__ void prep_kernel(const float* __restrict__ x, const float* __restrict__ w) {
    int bid = blockIdx.x;
    if (bid < CONV_BLOCKS) {
        int i = (bid * 256 + threadIdx.x) * 16;
        float4 v0 = *reinterpret_cast<const float4*>(x + i);
        float4 v1 = *reinterpret_cast<const float4*>(x + i + 4);
        float4 v2 = *reinterpret_cast<const float4*>(x + i + 8);
        float4 v3 = *reinterpret_cast<const float4*>(x + i + 12);
        __half2 h[8];
        h[0] = __floats2half2_rn(v0.x, v0.y); h[1] = __floats2half2_rn(v0.z, v0.w);
        h[2] = __floats2half2_rn(v1.x, v1.y); h[3] = __floats2half2_rn(v1.z, v1.w);
        h[4] = __floats2half2_rn(v2.x, v2.y); h[5] = __floats2half2_rn(v2.z, v2.w);
        h[6] = __floats2half2_rn(v3.x, v3.y); h[7] = __floats2half2_rn(v3.z, v3.w);
        *reinterpret_cast<uint4*>(d_Xh + i)     = *reinterpret_cast<uint4*>(h);
        *reinterpret_cast<uint4*>(d_Xh + i + 8) = *reinterpret_cast<uint4*>(h + 4);
    } else {
        int idx = (bid - CONV_BLOCKS) * 256 + threadIdx.x;   // F*F/2 half2 slots
        int n  = idx >> 9;
        int k2 = idx & 511;
        float f0 = w_at(w, 2 * k2,     n);
        float f1 = w_at(w, 2 * k2 + 1, n);
        reinterpret_cast<__half2*>(d_Wth)[idx] = __floats2half2_rn(f0, f1);
    }
}

__global__ void sigmoid_kernel(float* __restrict__ out) {
    int i = blockIdx.x * 256 + threadIdx.x;
    float z = 0.0f;
    #pragma unroll
    for (int j = 0; j < NBLK; ++j) z += d_part[j * BATCHN + i];
    out[i] = 1.0f / (1.0f + __expf(-z));
}

// ---------------- chunk compute body (ks-outer, direct accH accumulate) ----------------
template<bool TAIL>
__device__ __forceinline__ void chunk_body(uint32_t aAddr, uint32_t bAddr,
                                           uint32_t accH[2][8][2],
                                           int d, int warpN) {
    #pragma unroll
    for (int ks = 0; ks < 4; ++ks) {
        uint32_t a0[4], a1[4];
        ldsm4(a0, aAddr + ks * 32);
        ldsm4(a1, aAddr + 16 * ROW_B + ks * 32);
        #pragma unroll
        for (int g = 0; g < 4; ++g) {
            if (TAIL) {
                // whole (ks,g) step zero when k_lo >= n_hi of nt=2g+1 block
                if (!((d + 16 * ks) < (warpN * 64 + (2 * g + 1) * 8 + 8))) continue;
            }
            uint32_t b[4];
            ldsm4(b, bAddr + (uint32_t)(g * 16) * ROW_B + ks * 32);
            bool nz0 = !TAIL || ((d + 16 * ks) < (warpN * 64 + 2 * g * 8 + 8));
            if (nz0) {
                mma_h(accH[0][2 * g], a0, b[0], b[2]);
                mma_h(accH[1][2 * g], a1, b[0], b[2]);
            }
            mma_h(accH[0][2 * g + 1], a0, b[1], b[3]);
            mma_h(accH[1][2 * g + 1], a1, b[1], b[3]);
        }
    }
}

// ---------------- main GEMM + fused rowdot ----------------
extern __shared__ char smem_buf[];

__global__ void __launch_bounds__(NTHREADS, 3)
poly2_gemm_kernel() {
    uint32_t sb = smem_u32(smem_buf);
    float* part = reinterpret_cast<float*>(smem_buf + PART_OFF);

    int tid  = threadIdx.x;
    int lane = tid & 31;
    int wid  = tid >> 5;
    int warpM = wid & 3;
    int warpN = wid >> 2;
    int m0 = blockIdx.x * M_TILE;
    int by = (int)gridDim.y - 1 - (int)blockIdx.y;   // heavy tiles first
    int n0 = by * N_TILE;

    int nchunks = (n0 + N_TILE) / K_CHUNK;           // 2..16

    int lrow8 = tid >> 3, lcol8 = tid & 7;
    const __half* agp = d_Xh  + (size_t)(m0 + lrow8) * F + lcol8 * 8;
    const __half* bgp = d_Wth + (size_t)(n0 + lrow8) * F + lcol8 * 8;
    uint32_t sdoff = (uint32_t)(lrow8 * ROW_B + lcol8 * 16);

    #define ISSUE_STAGE(sidx)                                            \
        do {                                                             \
            uint32_t ab = sb + (uint32_t)(sidx) * STAGE_BYTES + sdoff;   \
            _Pragma("unroll")                                            \
            for (int j = 0; j < 4; ++j)                                  \
                cp16(ab + j * (32 * ROW_B), agp + j * (32 * F));         \
            uint32_t bb = ab + TILE_BYTES;                               \
            _Pragma("unroll")                                            \
            for (int j = 0; j < 4; ++j)                                  \
                cp16(bb + j * (32 * ROW_B), bgp + j * (32 * F));         \
            agp += K_CHUNK; bgp += K_CHUNK;                              \
        } while (0)

    uint32_t accH[2][8][2];
    #pragma unroll
    for (int mt = 0; mt < 2; ++mt)
        #pragma unroll
        for (int nt = 0; nt < 8; ++nt)
            accH[mt][nt][0] = accH[mt][nt][1] = 0u;

    ISSUE_STAGE(0); cp_commit();
    ISSUE_STAGE(1); cp_commit();

    uint32_t lrow  = (uint32_t)(lane & 15);
    uint32_t khalf = (uint32_t)((lane >> 4) * 16);
    uint32_t aoff = (uint32_t)(warpM * 32) * ROW_B + lrow * ROW_B + khalf;
    uint32_t boff = (uint32_t)(warpN * 64) * ROW_B + lrow * ROW_B + khalf + TILE_BYTES;

    for (int ck = 0; ck < nchunks; ++ck) {
        cp_wait1();               // stage ck landed (this thread's groups)
        __syncthreads();          // landed CTA-wide

        uint32_t stbase = sb + (uint32_t)(ck & 1) * STAGE_BYTES;
        if (ck < nchunks - 2)
            chunk_body<false>(stbase + aoff, stbase + boff, accH, 0, warpN);
        else
            chunk_body<true>(stbase + aoff, stbase + boff, accH,
                             64 * ck - n0, warpN);   // d in {0,64}

        __syncthreads();          // compute on buffer (ck&1) done CTA-wide
        if (ck + 2 < nchunks) {
            ISSUE_STAGE(ck & 1);
        }
        cp_commit();              // uniform group accounting
    }

    // ---------------- epilogue: rowdot S * x ----------------
    if (tid < 128) part[tid] = 0.0f;
    __syncthreads();

    #pragma unroll
    for (int mt = 0; mt < 2; ++mt) {
        float ps0 = 0.0f, ps1 = 0.0f;
        #pragma unroll
        for (int nt = 0; nt < 8; ++nt) {
            int col  = n0 + warpN * 64 + nt * 8 + (lane & 3) * 2;
            int rowg = m0 + warpM * 32 + mt * 16 + (lane >> 2);
            float2 x0 = __half22float2(*reinterpret_cast<const __half2*>(d_Xh + (size_t)rowg * F + col));
            float2 x1 = __half22float2(*reinterpret_cast<const __half2*>(d_Xh + (size_t)(rowg + 8) * F + col));
            float2 s0 = __half22float2(*reinterpret_cast<__half2*>(&accH[mt][nt][0]));
            float2 s1 = __half22float2(*reinterpret_cast<__half2*>(&accH[mt][nt][1]));
            ps0 += s0.x * x0.x + s0.y * x0.y;
            ps1 += s1.x * x1.x + s1.y * x1.y;
        }
        ps0 += __shfl_xor_sync(0xffffffffu, ps0, 1);
        ps0 += __shfl_xor_sync(0xffffffffu, ps0, 2);
        ps1 += __shfl_xor_sync(0xffffffffu, ps1, 1);
        ps1 += __shfl_xor_sync(0xffffffffu, ps1, 2);
        if ((lane & 3) == 0) {
            int rl = warpM * 32 + mt * 16 + (lane >> 2);
            atomicAdd(&part[rl], ps0);
            atomicAdd(&part[rl + 8], ps1);
        }
    }
    __syncthreads();
    if (tid < 128) d_part[by * BATCHN + m0 + tid] = part[tid];
}

// ---------------- launch ----------------
extern "C" void kernel_launch(void* const* d_in, const int* in_sizes, int n_in,
                              void* d_out, int out_size) {
    const float* x = (const float*)d_in[0];
    const float* w = (const float*)d_in[1];
    float* out = (float*)d_out;

    prep_kernel<<<CONV_BLOCKS + WT_BLOCKS, 256>>>(x, w);

    cudaFuncSetAttribute(poly2_gemm_kernel,
                         cudaFuncAttributeMaxDynamicSharedMemorySize, SMEM_TOTAL);
    dim3 grid(BATCHN / M_TILE, NBLK);
    poly2_gemm_kernel<<<grid, NTHREADS, SMEM_TOTAL>>>();

    sigmoid_kernel<<<BATCHN / 256, 256>>>(out);
}

// round 15
// speedup vs baseline: 1.3900x; 1.3900x over previous
#include <cuda_runtime.h>
#include <cuda_fp16.h>
#include <cstdint>
#include <math.h>

// POLY2: out_b = sigmoid( sum_{i<j} w_ij * x_bi * x_bj )
// R9 champion mainloop (fp16 mma m16n8k16, chunk-scoped fp16 chains, ldmatrix,
// 3-stage cp.async, 2 CTAs/SM, triangular+diagonal skip, heavy-first) with the
// final reduction+sigmoid fused into the GEMM via last-CTA-per-mblock pattern.

#define F        1024
#define BATCHN   16384
#define M_TILE   128
#define N_TILE   128
#define K_CHUNK  64
#define NTHREADS 256
#define NBLK     8
#define STAGES   3

#define ROW_B       144
#define TILE_BYTES  (128 * ROW_B)            // 18432
#define STAGE_BYTES (2 * TILE_BYTES)         // 36864
#define PART_OFF    (STAGES * STAGE_BYTES)   // 110592
#define SMEM_TOTAL  (PART_OFF + 128 * 4 + 16)

__device__ __half d_Xh[BATCHN * F];
__device__ __half d_Wth[F * F];           // Wt[n][k] = w_{k,n} (k<n else 0)
__device__ float  d_part[NBLK * BATCHN];
__device__ unsigned int d_cnt[BATCHN / M_TILE];   // per-mblock arrival counters

// ---------------- helpers ----------------
__device__ __forceinline__ uint32_t smem_u32(const void* p) {
    uint32_t a;
    asm("{ .reg .u64 t; cvta.to.shared.u64 t, %1; cvt.u32.u64 %0, t; }" : "=r"(a) : "l"(p));
    return a;
}
__device__ __forceinline__ void cp16(uint32_t dst, const void* src) {
    asm volatile("cp.async.cg.shared.global [%0], [%1], 16;" :: "r"(dst), "l"(src) : "memory");
}
__device__ __forceinline__ void cp_commit() { asm volatile("cp.async.commit_group;" ::: "memory"); }
__device__ __forceinline__ void cp_wait1()  { asm volatile("cp.async.wait_group 1;"  ::: "memory"); }

__device__ __forceinline__ void ldsm4(uint32_t* r, uint32_t addr) {
    asm volatile("ldmatrix.sync.aligned.m8n8.x4.shared.b16 {%0,%1,%2,%3}, [%4];"
        : "=r"(r[0]), "=r"(r[1]), "=r"(r[2]), "=r"(r[3]) : "r"(addr));
}
__device__ __forceinline__ void mma_h(uint32_t* c, const uint32_t* a, uint32_t b0, uint32_t b1) {
    asm volatile(
        "mma.sync.aligned.m16n8k16.row.col.f16.f16.f16.f16 "
        "{%0,%1}, {%2,%3,%4,%5}, {%6,%7}, {%0,%1};"
        : "+r"(c[0]), "+r"(c[1])
        : "r"(a[0]), "r"(a[1]), "r"(a[2]), "r"(a[3]), "r"(b0), "r"(b1));
}

// ---------------- merged prep (R9-proven 8 elems/thread) + counter zero ----------------
__device__ __forceinline__ float w_at(const float* __restrict__ w, int k, int n) {
    if (k >= n) return 0.0f;
    int pi = k * (F - 1) - (k * (k - 1)) / 2 + (n - k - 1);
    return w[pi];
}
#define CONV_BLOCKS (BATCHN * F / (256 * 8))          // 8192
#define WT_BLOCKS   (F * F / 2 / 256)                 // 2048

__global__ void prep_kernel(const float* __restrict__ x, const float* __restrict__ w) {
    int bid = blockIdx.x;
    if (bid == 0 && threadIdx.x < BATCHN / M_TILE)
        d_cnt[threadIdx.x] = 0u;                      // belt & suspenders (also self-reset)
    if (bid < CONV_BLOCKS) {
        int i = (bid * 256 + threadIdx.x) * 8;
        float4 v0 = *reinterpret_cast<const float4*>(x + i);
        float4 v1 = *reinterpret_cast<const float4*>(x + i + 4);
        __half2 h[4];
        h[0] = __floats2half2_rn(v0.x, v0.y);
        h[1] = __floats2half2_rn(v0.z, v0.w);
        h[2] = __floats2half2_rn(v1.x, v1.y);
        h[3] = __floats2half2_rn(v1.z, v1.w);
        *reinterpret_cast<uint4*>(d_Xh + i) = *reinterpret_cast<uint4*>(h);
    } else {
        int idx = (bid - CONV_BLOCKS) * 256 + threadIdx.x;   // F*F/2 half2 slots
        int n  = idx >> 9;
        int k2 = idx & 511;
        float f0 = w_at(w, 2 * k2,     n);
        float f1 = w_at(w, 2 * k2 + 1, n);
        reinterpret_cast<__half2*>(d_Wth)[idx] = __floats2half2_rn(f0, f1);
    }
}

// ---------------- chunk compute body (R9 verbatim) ----------------
template<bool TAIL>
__device__ __forceinline__ void chunk_body(uint32_t aAddr, uint32_t bAddr,
                                           uint32_t accH[2][8][2],
                                           int d, int warpN) {
    uint32_t a[2][4][4];
    #pragma unroll
    for (int ks = 0; ks < 4; ++ks) {
        ldsm4(a[0][ks], aAddr + ks * 32);
        ldsm4(a[1][ks], aAddr + 16 * ROW_B + ks * 32);
    }
    #pragma unroll
    for (int g = 0; g < 4; ++g) {
        uint32_t c[4][2] = {{0u,0u},{0u,0u},{0u,0u},{0u,0u}};
        #pragma unroll
        for (int ks = 0; ks < 4; ++ks) {
            if (TAIL) {
                if (!((d + 16 * ks) < (warpN * 64 + (2 * g + 1) * 8 + 8))) continue;
            }
            uint32_t b[4];
            ldsm4(b, bAddr + (uint32_t)(g * 16) * ROW_B + ks * 32);
            bool nz0 = !TAIL || ((d + 16 * ks) < (warpN * 64 + 2 * g * 8 + 8));
            if (nz0) {
                mma_h(c[0], a[0][ks], b[0], b[2]);
                mma_h(c[2], a[1][ks], b[0], b[2]);
            }
            mma_h(c[1], a[0][ks], b[1], b[3]);
            mma_h(c[3], a[1][ks], b[1], b[3]);
        }
        #pragma unroll
        for (int q = 0; q < 2; ++q) {
            #pragma unroll
            for (int r = 0; r < 2; ++r) {
                __half2 v0 = *reinterpret_cast<__half2*>(&c[2 * q][r]);
                __half2 v1 = *reinterpret_cast<__half2*>(&c[2 * q + 1][r]);
                __half2* A0 = reinterpret_cast<__half2*>(&accH[q][2 * g][r]);
                __half2* A1 = reinterpret_cast<__half2*>(&accH[q][2 * g + 1][r]);
                *A0 = __hadd2(*A0, v0);
                *A1 = __hadd2(*A1, v1);
            }
        }
    }
}

// ---------------- main GEMM + fused rowdot + fused final sigmoid ----------------
extern __shared__ char smem_buf[];

__global__ void __launch_bounds__(NTHREADS, 2)
poly2_gemm_kernel(float* __restrict__ out) {
    uint32_t sb = smem_u32(smem_buf);
    float* part = reinterpret_cast<float*>(smem_buf + PART_OFF);
    unsigned int* lastflag = reinterpret_cast<unsigned int*>(smem_buf + PART_OFF + 128 * 4);

    int tid  = threadIdx.x;
    int lane = tid & 31;
    int wid  = tid >> 5;
    int warpM = wid & 3;
    int warpN = wid >> 2;
    int m0 = blockIdx.x * M_TILE;
    int by = (int)gridDim.y - 1 - (int)blockIdx.y;   // heavy tiles first
    int n0 = by * N_TILE;

    int nchunks = (n0 + N_TILE) / K_CHUNK;           // 2..16

    int lrow8 = tid >> 3, lcol8 = tid & 7;
    const __half* agp = d_Xh  + (size_t)(m0 + lrow8) * F + lcol8 * 8;
    const __half* bgp = d_Wth + (size_t)(n0 + lrow8) * F + lcol8 * 8;
    uint32_t sdoff = (uint32_t)(lrow8 * ROW_B + lcol8 * 16);

    #define ISSUE_STAGE(sidx)                                            \
        do {                                                             \
            uint32_t ab = sb + (uint32_t)(sidx) * STAGE_BYTES + sdoff;   \
            _Pragma("unroll")                                            \
            for (int j = 0; j < 4; ++j)                                  \
                cp16(ab + j * (32 * ROW_B), agp + j * (32 * F));         \
            uint32_t bb = ab + TILE_BYTES;                               \
            _Pragma("unroll")                                            \
            for (int j = 0; j < 4; ++j)                                  \
                cp16(bb + j * (32 * ROW_B), bgp + j * (32 * F));         \
            agp += K_CHUNK; bgp += K_CHUNK;                              \
        } while (0)

    uint32_t accH[2][8][2];
    #pragma unroll
    for (int mt = 0; mt < 2; ++mt)
        #pragma unroll
        for (int nt = 0; nt < 8; ++nt)
            accH[mt][nt][0] = accH[mt][nt][1] = 0u;

    ISSUE_STAGE(0); cp_commit();
    ISSUE_STAGE(1); cp_commit();
    cp_wait1();
    __syncthreads();

    uint32_t lrow  = (uint32_t)(lane & 15);
    uint32_t khalf = (uint32_t)((lane >> 4) * 16);
    uint32_t aoff = (uint32_t)(warpM * 32) * ROW_B + lrow * ROW_B + khalf;
    uint32_t boff = (uint32_t)(warpN * 64) * ROW_B + lrow * ROW_B + khalf + TILE_BYTES;

    int sidx = 2;
    for (int ck = 0; ck < nchunks; ++ck) {
        if (ck + 2 < nchunks) {
            ISSUE_STAGE(sidx);
        }
        cp_commit();
        if (++sidx == STAGES) sidx = 0;

        uint32_t stbase = sb + (uint32_t)(ck % STAGES) * STAGE_BYTES;
        if (ck < nchunks - 2)
            chunk_body<false>(stbase + aoff, stbase + boff, accH, 0, warpN);
        else
            chunk_body<true>(stbase + aoff, stbase + boff, accH,
                             64 * ck - n0, warpN);   // d in {0,64}

        cp_wait1();
        __syncthreads();
    }

    // ---------------- epilogue: rowdot S * x ----------------
    if (tid < 128) part[tid] = 0.0f;
    __syncthreads();

    #pragma unroll
    for (int mt = 0; mt < 2; ++mt) {
        float ps0 = 0.0f, ps1 = 0.0f;
        #pragma unroll
        for (int nt = 0; nt < 8; ++nt) {
            int col  = n0 + warpN * 64 + nt * 8 + (lane & 3) * 2;
            int rowg = m0 + warpM * 32 + mt * 16 + (lane >> 2);
            float2 x0 = __half22float2(*reinterpret_cast<const __half2*>(d_Xh + (size_t)rowg * F + col));
            float2 x1 = __half22float2(*reinterpret_cast<const __half2*>(d_Xh + (size_t)(rowg + 8) * F + col));
            float2 s0 = __half22float2(*reinterpret_cast<__half2*>(&accH[mt][nt][0]));
            float2 s1 = __half22float2(*reinterpret_cast<__half2*>(&accH[mt][nt][1]));
            ps0 += s0.x * x0.x + s0.y * x0.y;
            ps1 += s1.x * x1.x + s1.y * x1.y;
        }
        ps0 += __shfl_xor_sync(0xffffffffu, ps0, 1);
        ps0 += __shfl_xor_sync(0xffffffffu, ps0, 2);
        ps1 += __shfl_xor_sync(0xffffffffu, ps1, 1);
        ps1 += __shfl_xor_sync(0xffffffffu, ps1, 2);
        if ((lane & 3) == 0) {
            int rl = warpM * 32 + mt * 16 + (lane >> 2);
            atomicAdd(&part[rl], ps0);
            atomicAdd(&part[rl + 8], ps1);
        }
    }
    __syncthreads();
    if (tid < 128) d_part[by * BATCHN + m0 + tid] = part[tid];

    // ---------------- fused final: last CTA of this m-block reduces + sigmoid ----------------
    __threadfence();                 // order d_part stores before the counter bump
    __syncthreads();                 // all threads' fences done
    if (tid == 0) {
        unsigned int old = atomicAdd(&d_cnt[blockIdx.x], 1u);
        *lastflag = (old == NBLK - 1) ? 1u : 0u;
    }
    __syncthreads();
    if (*lastflag) {
        __threadfence();             // acquire: see all other CTAs' d_part
        if (tid < 128) {
            int i = m0 + tid;
            float z = 0.0f;
            #pragma unroll
            for (int j = 0; j < NBLK; ++j) z += d_part[j * BATCHN + i];
            out[i] = 1.0f / (1.0f + __expf(-z));
        }
        if (tid == 0) d_cnt[blockIdx.x] = 0u;   // self-reset for graph replay
    }
}

// ---------------- launch ----------------
extern "C" void kernel_launch(void* const* d_in, const int* in_sizes, int n_in,
                              void* d_out, int out_size) {
    const float* x = (const float*)d_in[0];
    const float* w = (const float*)d_in[1];
    float* out = (float*)d_out;

    prep_kernel<<<CONV_BLOCKS + WT_BLOCKS, 256>>>(x, w);

    cudaFuncSetAttribute(poly2_gemm_kernel,
                         cudaFuncAttributeMaxDynamicSharedMemorySize, SMEM_TOTAL);
    dim3 grid(BATCHN / M_TILE, NBLK);
    poly2_gemm_kernel<<<grid, NTHREADS, SMEM_TOTAL>>>(out);
}

// round 17
// speedup vs baseline: 1.4690x; 1.0568x over previous
#include <cuda_runtime.h>
#include <cuda_fp16.h>
#include <cstdint>
#include <math.h>

// POLY2: out_b = sigmoid( sum_{i<j} w_ij * x_bi * x_bj )
// fp16 mma m16n8k16, DIRECT fp16 accumulation (C-operand), warp tile 64x64
// (128 B/MMA smem traffic vs 192 -> smem no longer co-limits the tensor pipe),
// CTA 256x128, 2 CTAs/SM x 8 warps = 16 warps/SM, 2-stage cp.async,
// triangular + diagonal skip, heavy-first, fused last-CTA sigmoid.

#define F        1024
#define BATCHN   16384
#define M_TILE   256
#define N_TILE   128
#define K_CHUNK  64
#define NTHREADS 256
#define NBLK     8

#define ROW_B        144
#define A_TILE_BYTES (256 * ROW_B)            // 36864
#define B_TILE_BYTES (128 * ROW_B)            // 18432
#define STAGE_BYTES  (A_TILE_BYTES + B_TILE_BYTES)   // 55296
#define PART_OFF     (2 * STAGE_BYTES)        // 110592
#define SMEM_TOTAL   (PART_OFF + 256 * 4 + 16)   // 111632 (x2 CTAs <= 228KB)

__device__ __half d_Xh[BATCHN * F];
__device__ __half d_Wth[F * F];           // Wt[n][k] = w_{k,n} (k<n else 0)
__device__ float  d_part[NBLK * BATCHN];
__device__ unsigned int d_cnt[BATCHN / M_TILE];   // 64 m-block counters

// ---------------- helpers ----------------
__device__ __forceinline__ uint32_t smem_u32(const void* p) {
    uint32_t a;
    asm("{ .reg .u64 t; cvta.to.shared.u64 t, %1; cvt.u32.u64 %0, t; }" : "=r"(a) : "l"(p));
    return a;
}
__device__ __forceinline__ void cp16(uint32_t dst, const void* src) {
    asm volatile("cp.async.cg.shared.global [%0], [%1], 16;" :: "r"(dst), "l"(src) : "memory");
}
__device__ __forceinline__ void cp_commit() { asm volatile("cp.async.commit_group;" ::: "memory"); }
__device__ __forceinline__ void cp_wait1()  { asm volatile("cp.async.wait_group 1;"  ::: "memory"); }

__device__ __forceinline__ void ldsm4(uint32_t* r, uint32_t addr) {
    asm volatile("ldmatrix.sync.aligned.m8n8.x4.shared.b16 {%0,%1,%2,%3}, [%4];"
        : "=r"(r[0]), "=r"(r[1]), "=r"(r[2]), "=r"(r[3]) : "r"(addr));
}
// fp16 mma, in-place running accumulation (C = D = accH)
__device__ __forceinline__ void mma_h(uint32_t* c, const uint32_t* a, uint32_t b0, uint32_t b1) {
    asm volatile(
        "mma.sync.aligned.m16n8k16.row.col.f16.f16.f16.f16 "
        "{%0,%1}, {%2,%3,%4,%5}, {%6,%7}, {%0,%1};"
        : "+r"(c[0]), "+r"(c[1])
        : "r"(a[0]), "r"(a[1]), "r"(a[2]), "r"(a[3]), "r"(b0), "r"(b1));
}

// ---------------- merged prep (proven 8 elems/thread) ----------------
__device__ __forceinline__ float w_at(const float* __restrict__ w, int k, int n) {
    if (k >= n) return 0.0f;
    int pi = k * (F - 1) - (k * (k - 1)) / 2 + (n - k - 1);
    return w[pi];
}
#define CONV_BLOCKS (BATCHN * F / (256 * 8))          // 8192
#define WT_BLOCKS   (F * F / 2 / 256)                 // 2048

__global__ void prep_kernel(const float* __restrict__ x, const float* __restrict__ w) {
    int bid = blockIdx.x;
    if (bid == 0 && threadIdx.x < BATCHN / M_TILE)
        d_cnt[threadIdx.x] = 0u;
    if (bid < CONV_BLOCKS) {
        int i = (bid * 256 + threadIdx.x) * 8;
        float4 v0 = *reinterpret_cast<const float4*>(x + i);
        float4 v1 = *reinterpret_cast<const float4*>(x + i + 4);
        __half2 h[4];
        h[0] = __floats2half2_rn(v0.x, v0.y);
        h[1] = __floats2half2_rn(v0.z, v0.w);
        h[2] = __floats2half2_rn(v1.x, v1.y);
        h[3] = __floats2half2_rn(v1.z, v1.w);
        *reinterpret_cast<uint4*>(d_Xh + i) = *reinterpret_cast<uint4*>(h);
    } else {
        int idx = (bid - CONV_BLOCKS) * 256 + threadIdx.x;
        int n  = idx >> 9;
        int k2 = idx & 511;
        float f0 = w_at(w, 2 * k2,     n);
        float f1 = w_at(w, 2 * k2 + 1, n);
        reinterpret_cast<__half2*>(d_Wth)[idx] = __floats2half2_rn(f0, f1);
    }
}

// ---------------- chunk compute body (ks-outer, direct accH) ----------------
template<bool TAIL>
__device__ __forceinline__ void chunk_body(uint32_t aAddr, uint32_t bAddr,
                                           uint32_t accH[4][8][2],
                                           int d, int warpN) {
    #pragma unroll
    for (int ks = 0; ks < 4; ++ks) {
        uint32_t a[4][4];
        #pragma unroll
        for (int mt = 0; mt < 4; ++mt)
            ldsm4(a[mt], aAddr + (uint32_t)(mt * 16) * ROW_B + ks * 32);
        #pragma unroll
        for (int g = 0; g < 4; ++g) {
            if (TAIL) {
                // whole (ks,g) step zero when k_lo >= n_hi of nt=2g+1 block
                if (!((d + 16 * ks) < (warpN * 64 + (2 * g + 1) * 8 + 8))) continue;
            }
            uint32_t b[4];
            ldsm4(b, bAddr + (uint32_t)(g * 16) * ROW_B + ks * 32);
            bool nz0 = !TAIL || ((d + 16 * ks) < (warpN * 64 + 2 * g * 8 + 8));
            #pragma unroll
            for (int mt = 0; mt < 4; ++mt) {
                if (nz0) mma_h(accH[mt][2 * g], a[mt], b[0], b[2]);
                mma_h(accH[mt][2 * g + 1], a[mt], b[1], b[3]);
            }
        }
    }
}

// ---------------- main GEMM + fused rowdot + fused final sigmoid ----------------
extern __shared__ char smem_buf[];

__global__ void __launch_bounds__(NTHREADS, 2)
poly2_gemm_kernel(float* __restrict__ out) {
    uint32_t sb = smem_u32(smem_buf);
    float* part = reinterpret_cast<float*>(smem_buf + PART_OFF);
    unsigned int* lastflag = reinterpret_cast<unsigned int*>(smem_buf + PART_OFF + 256 * 4);

    int tid  = threadIdx.x;
    int lane = tid & 31;
    int wid  = tid >> 5;
    int warpM = wid & 3;                 // 4 warps along M (tile 64)
    int warpN = wid >> 2;                // 2 warps along N (tile 64)
    int m0 = blockIdx.x * M_TILE;
    int by = (int)gridDim.y - 1 - (int)blockIdx.y;   // heavy tiles first
    int n0 = by * N_TILE;

    int nchunks = (n0 + N_TILE) / K_CHUNK;           // 2..16

    // loader: A 256 rows x 8 chunks, B 128 rows x 8 chunks (16B each)
    int lrow8 = tid >> 3, lcol8 = tid & 7;
    const __half* agp = d_Xh  + (size_t)(m0 + lrow8) * F + lcol8 * 8;
    const __half* bgp = d_Wth + (size_t)(n0 + lrow8) * F + lcol8 * 8;
    uint32_t sdoff = (uint32_t)(lrow8 * ROW_B + lcol8 * 16);

    #define ISSUE_STAGE(sidx)                                            \
        do {                                                             \
            uint32_t ab = sb + (uint32_t)(sidx) * STAGE_BYTES + sdoff;   \
            _Pragma("unroll")                                            \
            for (int j = 0; j < 8; ++j)      /* A: 256 rows */           \
                cp16(ab + j * (32 * ROW_B), agp + j * (32 * F));         \
            uint32_t bb = ab + A_TILE_BYTES;                             \
            _Pragma("unroll")                                            \
            for (int j = 0; j < 4; ++j)      /* B: 128 rows */           \
                cp16(bb + j * (32 * ROW_B), bgp + j * (32 * F));         \
            agp += K_CHUNK; bgp += K_CHUNK;                              \
        } while (0)

    uint32_t accH[4][8][2];
    #pragma unroll
    for (int mt = 0; mt < 4; ++mt)
        #pragma unroll
        for (int nt = 0; nt < 8; ++nt)
            accH[mt][nt][0] = accH[mt][nt][1] = 0u;

    ISSUE_STAGE(0); cp_commit();
    ISSUE_STAGE(1); cp_commit();

    uint32_t lrow  = (uint32_t)(lane & 15);
    uint32_t khalf = (uint32_t)((lane >> 4) * 16);
    uint32_t aoff = (uint32_t)(warpM * 64) * ROW_B + lrow * ROW_B + khalf;
    uint32_t boff = (uint32_t)(warpN * 64) * ROW_B + lrow * ROW_B + khalf + A_TILE_BYTES;

    for (int ck = 0; ck < nchunks; ++ck) {
        cp_wait1();               // stage ck landed (this thread's groups)
        __syncthreads();          // landed CTA-wide

        uint32_t stbase = sb + (uint32_t)(ck & 1) * STAGE_BYTES;
        if (ck < nchunks - 2)
            chunk_body<false>(stbase + aoff, stbase + boff, accH, 0, warpN);
        else
            chunk_body<true>(stbase + aoff, stbase + boff, accH,
                             64 * ck - n0, warpN);   // d in {0,64}

        __syncthreads();          // compute on buffer (ck&1) done CTA-wide
        if (ck + 2 < nchunks) {
            ISSUE_STAGE(ck & 1);
        }
        cp_commit();              // uniform group accounting
    }

    // ---------------- epilogue: rowdot S * x ----------------
    part[tid] = 0.0f;
    __syncthreads();

    #pragma unroll
    for (int mt = 0; mt < 4; ++mt) {
        float ps0 = 0.0f, ps1 = 0.0f;
        #pragma unroll
        for (int nt = 0; nt < 8; ++nt) {
            int col  = n0 + warpN * 64 + nt * 8 + (lane & 3) * 2;
            int rowg = m0 + warpM * 64 + mt * 16 + (lane >> 2);
            float2 x0 = __half22float2(*reinterpret_cast<const __half2*>(d_Xh + (size_t)rowg * F + col));
            float2 x1 = __half22float2(*reinterpret_cast<const __half2*>(d_Xh + (size_t)(rowg + 8) * F + col));
            float2 s0 = __half22float2(*reinterpret_cast<__half2*>(&accH[mt][nt][0]));
            float2 s1 = __half22float2(*reinterpret_cast<__half2*>(&accH[mt][nt][1]));
            ps0 += s0.x * x0.x + s0.y * x0.y;
            ps1 += s1.x * x1.x + s1.y * x1.y;
        }
        ps0 += __shfl_xor_sync(0xffffffffu, ps0, 1);
        ps0 += __shfl_xor_sync(0xffffffffu, ps0, 2);
        ps1 += __shfl_xor_sync(0xffffffffu, ps1, 1);
        ps1 += __shfl_xor_sync(0xffffffffu, ps1, 2);
        if ((lane & 3) == 0) {
            int rl = warpM * 64 + mt * 16 + (lane >> 2);
            atomicAdd(&part[rl], ps0);
            atomicAdd(&part[rl + 8], ps1);
        }
    }
    __syncthreads();
    d_part[by * BATCHN + m0 + tid] = part[tid];

    // ---------------- fused final: last CTA of this m-block reduces + sigmoid ----------------
    __threadfence();
    __syncthreads();
    if (tid == 0) {
        unsigned int old = atomicAdd(&d_cnt[blockIdx.x], 1u);
        *lastflag = (old == NBLK - 1) ? 1u : 0u;
    }
    __syncthreads();
    if (*lastflag) {
        __threadfence();
        int i = m0 + tid;
        float z = 0.0f;
        #pragma unroll
        for (int j = 0; j < NBLK; ++j) z += d_part[j * BATCHN + i];
        out[i] = 1.0f / (1.0f + __expf(-z));
        if (tid == 0) d_cnt[blockIdx.x] = 0u;   // self-reset for graph replay
    }
}

// ---------------- launch ----------------
extern "C" void kernel_launch(void* const* d_in, const int* in_sizes, int n_in,
                              void* d_out, int out_size) {
    const float* x = (const float*)d_in[0];
    const float* w = (const float*)d_in[1];
    float* out = (float*)d_out;

    prep_kernel<<<CONV_BLOCKS + WT_BLOCKS, 256>>>(x, w);

    cudaFuncSetAttribute(poly2_gemm_kernel,
                         cudaFuncAttributeMaxDynamicSharedMemorySize, SMEM_TOTAL);
    dim3 grid(BATCHN / M_TILE, NBLK);           // 64 x 8
    poly2_gemm_kernel<<<grid, NTHREADS, SMEM_TOTAL>>>(out);
}